// round 15
// baseline (speedup 1.0000x reference)
#include <cuda_runtime.h>
#include <cuda_bf16.h>
#include <math.h>
#include <stdint.h>

// Problem constants (fixed by the dataset)
#define NN 169343            // nodes
#define NE 1166243           // edges
#define ET (NE + NN)         // edges + self loops = 1335586
#define FDIM 128
#define NCLS 40
#define NTILES ((NN + 127) / 128)   // 1324

#define ROWS_PAD 136         // bf16 elements per padded row
#define ROWB 272             // bytes per padded row

// ---------------- device scratch (no cudaMalloc allowed) ----------------
__device__ int   g_is64;
__device__ int   g_deg[NN];
__device__ int   g_fill[NN];
__device__ int   g_rowptr[NN + 1];
__device__ int   g_bsum[256];
__device__ int   g_adj[ET];
__device__ float g_dinv[NN];
__device__ float g_c[NCLS];               // c = b2 @ W3
__device__ float g_ta[(size_t)NN * FDIM]; // t1; later reused as u = t2@W3 (40-wide)
__device__ float g_tb[(size_t)NN * FDIM]; // t2
__device__ float g_l[(size_t)NN * NCLS];  // layer-3 conv output l

// Pre-packed bf16 weight images ([n][k], padded rows, hi/lo split)
__device__ unsigned short g_Bh1[128 * ROWS_PAD], g_Bl1[128 * ROWS_PAD];
__device__ unsigned short g_Bh2[128 * ROWS_PAD], g_Bl2[128 * ROWS_PAD];
__device__ unsigned short g_Bh3[40 * ROWS_PAD],  g_Bl3[40 * ROWS_PAD];

// ---------------- PTX helpers (portable sm_80+ class only) ----------------
__device__ __forceinline__ uint32_t smem_u32(const void* p) {
    uint32_t a;
    asm("{ .reg .u64 t; cvta.to.shared.u64 t, %1; cvt.u32.u64 %0, t; }"
        : "=r"(a) : "l"(p));
    return a;
}

__device__ __forceinline__ void ldsm_x4(uint32_t& r0, uint32_t& r1,
                                        uint32_t& r2, uint32_t& r3, uint32_t addr) {
    asm volatile("ldmatrix.sync.aligned.m8n8.x4.shared.b16 {%0,%1,%2,%3}, [%4];"
                 : "=r"(r0), "=r"(r1), "=r"(r2), "=r"(r3) : "r"(addr));
}

__device__ __forceinline__ void ldsm_x2(uint32_t& r0, uint32_t& r1, uint32_t addr) {
    asm volatile("ldmatrix.sync.aligned.m8n8.x2.shared.b16 {%0,%1}, [%2];"
                 : "=r"(r0), "=r"(r1) : "r"(addr));
}

__device__ __forceinline__ void mma_bf16(float& d0, float& d1, float& d2, float& d3,
                                         uint32_t a0, uint32_t a1, uint32_t a2, uint32_t a3,
                                         uint32_t b0, uint32_t b1) {
    asm volatile(
        "mma.sync.aligned.m16n8k16.row.col.f32.bf16.bf16.f32 "
        "{%0,%1,%2,%3}, {%4,%5,%6,%7}, {%8,%9}, {%0,%1,%2,%3};"
        : "+f"(d0), "+f"(d1), "+f"(d2), "+f"(d3)
        : "r"(a0), "r"(a1), "r"(a2), "r"(a3), "r"(b0), "r"(b1));
}

// split fp32 float4 -> bf16 hi/lo packed uint2 pair
__device__ __forceinline__ void split4(const float4& v, uint2& hi, uint2& lo) {
    unsigned short h0, h1, h2, h3;
    asm("cvt.rn.bf16.f32 %0, %1;" : "=h"(h0) : "f"(v.x));
    asm("cvt.rn.bf16.f32 %0, %1;" : "=h"(h1) : "f"(v.y));
    asm("cvt.rn.bf16.f32 %0, %1;" : "=h"(h2) : "f"(v.z));
    asm("cvt.rn.bf16.f32 %0, %1;" : "=h"(h3) : "f"(v.w));
    float r0 = v.x - __uint_as_float((unsigned)h0 << 16);
    float r1 = v.y - __uint_as_float((unsigned)h1 << 16);
    float r2 = v.z - __uint_as_float((unsigned)h2 << 16);
    float r3 = v.w - __uint_as_float((unsigned)h3 << 16);
    hi.x = (uint32_t)h0 | ((uint32_t)h1 << 16);
    hi.y = (uint32_t)h2 | ((uint32_t)h3 << 16);
    asm("cvt.rn.bf16x2.f32 %0, %1, %2;" : "=r"(lo.x) : "f"(r1), "f"(r0));
    asm("cvt.rn.bf16x2.f32 %0, %1, %2;" : "=r"(lo.y) : "f"(r3), "f"(r2));
}

__device__ __forceinline__ int edge_src(const int* w, int e) {
    return g_is64 ? w[2 * e] : w[e];
}
__device__ __forceinline__ int edge_dst(const int* w, int e) {
    return g_is64 ? w[2 * (NE + e)] : w[NE + e];
}

// ---------------- preprocessing ----------------
__global__ void init_deg_kernel(const int* __restrict__ w) {
    int i = blockIdx.x * blockDim.x + threadIdx.x;
    if (i < NN) { g_deg[i] = 1; g_fill[i] = 0; }
    if (blockIdx.x == 0) {
        __shared__ int bad;
        if (threadIdx.x == 0) bad = 0;
        __syncthreads();
        for (int j = threadIdx.x; j < 1024; j += blockDim.x)
            if (w[2 * j + 1] != 0) atomicAdd(&bad, 1);
        __syncthreads();
        if (threadIdx.x == 0) g_is64 = (bad == 0) ? 1 : 0;
    }
}

__global__ void count_deg_kernel(const int* __restrict__ w) {
    int e = blockIdx.x * blockDim.x + threadIdx.x;
    if (e >= NE) return;
    atomicAdd(&g_deg[edge_dst(w, e)], 1);
}

#define SCAN_BLK 1024
#define NB_SCAN ((NN + SCAN_BLK - 1) / SCAN_BLK)   // 166

__global__ void scan1_kernel() {   // also computes dinv
    __shared__ int sh[SCAN_BLK];
    int i = blockIdx.x * SCAN_BLK + threadIdx.x;
    int v = (i < NN) ? g_deg[i] : 0;
    if (i < NN) g_dinv[i] = rsqrtf((float)v);
    sh[threadIdx.x] = v;
    __syncthreads();
    for (int off = 1; off < SCAN_BLK; off <<= 1) {
        int add = (threadIdx.x >= off) ? sh[threadIdx.x - off] : 0;
        __syncthreads();
        sh[threadIdx.x] += add;
        __syncthreads();
    }
    if (i < NN) g_rowptr[i + 1] = sh[threadIdx.x];
    if (threadIdx.x == SCAN_BLK - 1) g_bsum[blockIdx.x] = sh[threadIdx.x];
}

// merged scan2+scan3
__global__ void scan3_kernel() {
    __shared__ int sh[256];
    int t = threadIdx.x;
    sh[t] = (t < NB_SCAN) ? g_bsum[t] : 0;
    __syncthreads();
#pragma unroll
    for (int off = 1; off < 256; off <<= 1) {
        int add = (t >= off) ? sh[t - off] : 0;
        __syncthreads();
        sh[t] += add;
        __syncthreads();
    }
    int pref = (blockIdx.x == 0) ? 0 : sh[blockIdx.x - 1];
    if (blockIdx.x * SCAN_BLK + t == 0) g_rowptr[0] = 0;
#pragma unroll
    for (int rep = 0; rep < SCAN_BLK / 256; rep++) {
        int ii = blockIdx.x * SCAN_BLK + rep * 256 + t;
        if (ii < NN) g_rowptr[ii + 1] += pref;
    }
}

__global__ void fill_adj_kernel(const int* __restrict__ w) {
    int e = blockIdx.x * blockDim.x + threadIdx.x;
    if (e >= ET) return;
    int s, d;
    if (e < NE) { s = edge_src(w, e); d = edge_dst(w, e); }
    else        { s = d = e - NE; }
    int pos = g_rowptr[d] + atomicAdd(&g_fill[d], 1);
    g_adj[pos] = s;
}

// ---------------- weight pre-pack (all three + c = b2@W3, one launch) ----------------
__global__ void pack_all_kernel(const float* __restrict__ W1,
                                const float* __restrict__ W2,
                                const float* __restrict__ W3,
                                const float* __restrict__ b2) {
    int idx = blockIdx.x * blockDim.x + threadIdx.x;
    if (idx >= 37888 + NCLS) return;
    if (idx >= 37888) {
        int n = idx - 37888;
        float acc = 0.f;
        for (int k = 0; k < FDIM; k++)
            acc += b2[k] * W3[k * NCLS + n];
        g_c[n] = acc;
        return;
    }
    const float* W;
    unsigned short *bh, *bl;
    int Nout;
    if (idx < 16384)        { W = W1; bh = g_Bh1; bl = g_Bl1; Nout = 128; }
    else if (idx < 32768)   { idx -= 16384; W = W2; bh = g_Bh2; bl = g_Bl2; Nout = 128; }
    else                    { idx -= 32768; W = W3; bh = g_Bh3; bl = g_Bl3; Nout = 40; }
    int n = idx >> 7, k = idx & 127;
    float v = W[k * Nout + n];
    unsigned short h; asm("cvt.rn.bf16.f32 %0, %1;" : "=h"(h) : "f"(v));
    float hf = __uint_as_float(((unsigned)h) << 16);
    float rres = v - hf;
    unsigned short l; asm("cvt.rn.bf16.f32 %0, %1;" : "=h"(l) : "f"(rres));
    bh[n * ROWS_PAD + k] = h;
    bl[n * ROWS_PAD + k] = l;
}

// smem layout: AHI @0 (34816), ALO @34816, BHI @69632, BLO @69632+BBYTES
#define AHI_OFF 0
#define ALO_OFF 34816
#define BHI_OFF 69632

// ---------------- GEMM1: g_ta = dinv[row] * (x @ W1) ----------------
__global__ void __launch_bounds__(512, 1)
gemm1_kernel(const float* __restrict__ A, int M) {
    extern __shared__ __align__(16) char smem[];
    const int BLO_OFF = BHI_OFF + 128 * ROWB;
    const uint32_t sb = smem_u32(smem);
    const int tid = threadIdx.x, wid = tid >> 5, lane = tid & 31;

    for (int i = tid; i < (128 * ROWB) / 16; i += 512) {
        ((float4*)(smem + BHI_OFF))[i] = ((const float4*)g_Bh1)[i];
        ((float4*)(smem + BLO_OFF))[i] = ((const float4*)g_Bl1)[i];
    }

    const int m0 = (wid & 7) * 16;
    const int n0 = (wid >> 3) * 64;
    const int a_r = lane & 15, a_kh = lane >> 4;
    const int b_r = lane & 7,  b_kh = (lane >> 3) & 1;

    for (int tile = blockIdx.x; tile < NTILES; tile += gridDim.x) {
        const int row0 = tile * 128;

#pragma unroll
        for (int i = 0; i < 8; i++) {
            int idx = tid + i * 512;
            int r = idx >> 5, c4 = (idx & 31) << 2;
            int grow = row0 + r;
            float4 v = make_float4(0.f, 0.f, 0.f, 0.f);
            if (grow < M) v = *(const float4*)(A + (size_t)grow * FDIM + c4);
            uint2 hi, lo; split4(v, hi, lo);
            int off = r * ROWB + c4 * 2;
            *(uint2*)(smem + AHI_OFF + off) = hi;
            *(uint2*)(smem + ALO_OFF + off) = lo;
        }
        __syncthreads();

        float acc[8][4];
#pragma unroll
        for (int nt = 0; nt < 8; nt++)
#pragma unroll
            for (int j = 0; j < 4; j++) acc[nt][j] = 0.f;

#pragma unroll
        for (int ks = 0; ks < 8; ks++) {
            const int k0 = ks * 16;
            uint32_t ah[4], al[4];
            uint32_t aoff = (uint32_t)((m0 + a_r) * ROWB + (k0 + a_kh * 8) * 2);
            ldsm_x4(ah[0], ah[1], ah[2], ah[3], sb + AHI_OFF + aoff);
            ldsm_x4(al[0], al[1], al[2], al[3], sb + ALO_OFF + aoff);
#pragma unroll
            for (int nt = 0; nt < 8; nt++) {
                uint32_t boff = (uint32_t)((n0 + nt * 8 + b_r) * ROWB + (k0 + b_kh * 8) * 2);
                uint32_t bh0, bh1, bl0, bl1;
                ldsm_x2(bh0, bh1, sb + BHI_OFF + boff);
                ldsm_x2(bl0, bl1, sb + BLO_OFF + boff);
                mma_bf16(acc[nt][0], acc[nt][1], acc[nt][2], acc[nt][3],
                         ah[0], ah[1], ah[2], ah[3], bh0, bh1);
                mma_bf16(acc[nt][0], acc[nt][1], acc[nt][2], acc[nt][3],
                         ah[0], ah[1], ah[2], ah[3], bl0, bl1);
                mma_bf16(acc[nt][0], acc[nt][1], acc[nt][2], acc[nt][3],
                         al[0], al[1], al[2], al[3], bh0, bh1);
            }
        }
        __syncthreads();

        const int qr = lane >> 2, qc = (lane & 3) * 2;
        int r_a = row0 + m0 + qr, r_b = r_a + 8;
        float dna = (r_a < M) ? g_dinv[r_a] : 0.f;
        float dnb = (r_b < M) ? g_dinv[r_b] : 0.f;
#pragma unroll
        for (int nt = 0; nt < 8; nt++) {
            int col = n0 + nt * 8 + qc;
            if (r_a < M)
                *(float2*)(g_ta + (size_t)r_a * FDIM + col) =
                    make_float2(acc[nt][0] * dna, acc[nt][1] * dna);
            if (r_b < M)
                *(float2*)(g_ta + (size_t)r_b * FDIM + col) =
                    make_float2(acc[nt][2] * dnb, acc[nt][3] * dnb);
        }
    }
}

// ---------------- fused2: t2 = dinv*( relu(dinv*agg(t1)+b1) @ W2 ) ----------------
// Gather uses cross-row interleaving: Phase A drains high-degree rows with
// 8-edge batches; Phase B round-robins 2 edges per row across the warp's
// 8 rows, keeping up to 16 loads in flight even at average degree ~8.
__global__ void __launch_bounds__(512, 1)
fused2_kernel(const float* __restrict__ bias, int M) {
    extern __shared__ __align__(16) char smem[];
    const int BBYTES = 128 * ROWB;
    const int BLO_OFF = BHI_OFF + BBYTES;
    const uint32_t sb = smem_u32(smem);
    const int tid = threadIdx.x, wid = tid >> 5, lane = tid & 31;

    const float* __restrict__ src = g_ta;
    float* __restrict__ out = g_tb;

    for (int i = tid; i < BBYTES / 16; i += 512) {
        ((float4*)(smem + BHI_OFF))[i] = ((const float4*)g_Bh2)[i];
        ((float4*)(smem + BLO_OFF))[i] = ((const float4*)g_Bl2)[i];
    }

    const int m0 = (wid & 7) * 16;
    const int n0 = (wid >> 3) * 64;
    const int a_r = lane & 15, a_kh = lane >> 4;
    const int b_r = lane & 7,  b_kh = (lane >> 3) & 1;

    const float4 bv = __ldg((const float4*)bias + lane);

    for (int tile = blockIdx.x; tile < NTILES; tile += gridDim.x) {
        const int row0 = tile * 128;

        // ---- gather phase: 8 rows per warp, cross-row interleaved ----
        float4 gacc[8];
        int ge[8], gn[8];
#pragma unroll
        for (int r = 0; r < 8; r++) {
            gacc[r] = make_float4(0.f, 0.f, 0.f, 0.f);
            int node = row0 + wid * 8 + r;
            if (node < M) { ge[r] = g_rowptr[node]; gn[r] = g_rowptr[node + 1]; }
            else          { ge[r] = 0; gn[r] = 0; }
        }

        // Phase A: per-row 8-edge batches while >=16 edges remain (rare, high degree)
#pragma unroll
        for (int r = 0; r < 8; r++) {
            while (ge[r] + 16 <= gn[r]) {
                int s[8];
#pragma unroll
                for (int j = 0; j < 8; j++) s[j] = __ldg(g_adj + ge[r] + j);
                float4 v[8];
#pragma unroll
                for (int j = 0; j < 8; j++)
                    v[j] = __ldg((const float4*)(src + (size_t)s[j] * FDIM) + lane);
#pragma unroll
                for (int j = 0; j < 8; j++) {
                    gacc[r].x += v[j].x; gacc[r].y += v[j].y;
                    gacc[r].z += v[j].z; gacc[r].w += v[j].w;
                }
                ge[r] += 8;
            }
        }

        // Phase B: interleaved rounds, up to 2 edges per row per round
        for (;;) {
            bool any = false;
#pragma unroll
            for (int r = 0; r < 8; r++) {
                int rem = gn[r] - ge[r];
                if (rem >= 2) {
                    int s0 = __ldg(g_adj + ge[r]);
                    int s1 = __ldg(g_adj + ge[r] + 1);
                    float4 v0 = __ldg((const float4*)(src + (size_t)s0 * FDIM) + lane);
                    float4 v1 = __ldg((const float4*)(src + (size_t)s1 * FDIM) + lane);
                    gacc[r].x += v0.x + v1.x; gacc[r].y += v0.y + v1.y;
                    gacc[r].z += v0.z + v1.z; gacc[r].w += v0.w + v1.w;
                    ge[r] += 2;
                    any = true;
                } else if (rem == 1) {
                    int s0 = __ldg(g_adj + ge[r]);
                    float4 v0 = __ldg((const float4*)(src + (size_t)s0 * FDIM) + lane);
                    gacc[r].x += v0.x; gacc[r].y += v0.y;
                    gacc[r].z += v0.z; gacc[r].w += v0.w;
                    ge[r] += 1;
                    any = true;
                }
            }
            if (!any) break;
        }

        // epilogue of gather: bias/relu/scale + store split to smem
#pragma unroll
        for (int r = 0; r < 8; r++) {
            int lr = wid * 8 + r;
            int node = row0 + lr;
            float4 acc = gacc[r];
            if (node < M) {
                float dn = g_dinv[node];
                acc.x = fmaf(acc.x, dn, bv.x);
                acc.y = fmaf(acc.y, dn, bv.y);
                acc.z = fmaf(acc.z, dn, bv.z);
                acc.w = fmaf(acc.w, dn, bv.w);
                acc.x = fmaxf(acc.x, 0.f); acc.y = fmaxf(acc.y, 0.f);
                acc.z = fmaxf(acc.z, 0.f); acc.w = fmaxf(acc.w, 0.f);
            } else {
                acc = make_float4(0.f, 0.f, 0.f, 0.f);
            }
            uint2 hi, lo; split4(acc, hi, lo);
            int off = lr * ROWB + lane * 8;
            *(uint2*)(smem + AHI_OFF + off) = hi;
            *(uint2*)(smem + ALO_OFF + off) = lo;
        }
        __syncthreads();

        // ---- MMA phase ----
        float acc[8][4];
#pragma unroll
        for (int nt = 0; nt < 8; nt++)
#pragma unroll
            for (int j = 0; j < 4; j++) acc[nt][j] = 0.f;

#pragma unroll
        for (int ks = 0; ks < 8; ks++) {
            const int k0 = ks * 16;
            uint32_t ah[4], al[4];
            uint32_t aoff = (uint32_t)((m0 + a_r) * ROWB + (k0 + a_kh * 8) * 2);
            ldsm_x4(ah[0], ah[1], ah[2], ah[3], sb + AHI_OFF + aoff);
            ldsm_x4(al[0], al[1], al[2], al[3], sb + ALO_OFF + aoff);
#pragma unroll
            for (int nt = 0; nt < 8; nt++) {
                uint32_t boff = (uint32_t)((n0 + nt * 8 + b_r) * ROWB + (k0 + b_kh * 8) * 2);
                uint32_t bh0, bh1, bl0, bl1;
                ldsm_x2(bh0, bh1, sb + BHI_OFF + boff);
                ldsm_x2(bl0, bl1, sb + BLO_OFF + boff);
                mma_bf16(acc[nt][0], acc[nt][1], acc[nt][2], acc[nt][3],
                         ah[0], ah[1], ah[2], ah[3], bh0, bh1);
                mma_bf16(acc[nt][0], acc[nt][1], acc[nt][2], acc[nt][3],
                         ah[0], ah[1], ah[2], ah[3], bl0, bl1);
                mma_bf16(acc[nt][0], acc[nt][1], acc[nt][2], acc[nt][3],
                         al[0], al[1], al[2], al[3], bh0, bh1);
            }
        }
        __syncthreads();

        const int qr = lane >> 2, qc = (lane & 3) * 2;
        int r_a = row0 + m0 + qr, r_b = r_a + 8;
        float dna = (r_a < M) ? g_dinv[r_a] : 0.f;
        float dnb = (r_b < M) ? g_dinv[r_b] : 0.f;
#pragma unroll
        for (int nt = 0; nt < 8; nt++) {
            int col = n0 + nt * 8 + qc;
            if (r_a < M)
                *(float2*)(out + (size_t)r_a * FDIM + col) =
                    make_float2(acc[nt][0] * dna, acc[nt][1] * dna);
            if (r_b < M)
                *(float2*)(out + (size_t)r_b * FDIM + col) =
                    make_float2(acc[nt][2] * dnb, acc[nt][3] * dnb);
        }
    }
}

// ---------------- GEMM3: u = t2 @ W3 (plain, 40-wide, u stored in g_ta) ----------------
__global__ void __launch_bounds__(512, 2)
gemm3_kernel(int M) {
    extern __shared__ __align__(16) char smem[];
    const int BBYTES = 40 * ROWB;
    const int BLO_OFF = BHI_OFF + BBYTES;
    const uint32_t sb = smem_u32(smem);
    const int tid = threadIdx.x, wid = tid >> 5, lane = tid & 31;

    const float* __restrict__ A = g_tb;
    float* __restrict__ out = g_ta;   // u, row stride NCLS

    for (int i = tid; i < BBYTES / 16; i += 512) {
        ((float4*)(smem + BHI_OFF))[i] = ((const float4*)g_Bh3)[i];
        ((float4*)(smem + BLO_OFF))[i] = ((const float4*)g_Bl3)[i];
    }

    const int m0 = (wid & 7) * 16;
    const int nhalf = wid >> 3;
    const int n0 = nhalf * 24;
    const int NT = nhalf ? 2 : 3;
    const int a_r = lane & 15, a_kh = lane >> 4;
    const int b_r = lane & 7,  b_kh = (lane >> 3) & 1;

    for (int tile = blockIdx.x; tile < NTILES; tile += gridDim.x) {
        const int row0 = tile * 128;

#pragma unroll
        for (int i = 0; i < 8; i++) {
            int idx = tid + i * 512;
            int r = idx >> 5, c4 = (idx & 31) << 2;
            int grow = row0 + r;
            float4 v = make_float4(0.f, 0.f, 0.f, 0.f);
            if (grow < M) v = *(const float4*)(A + (size_t)grow * FDIM + c4);
            uint2 hi, lo; split4(v, hi, lo);
            int off = r * ROWB + c4 * 2;
            *(uint2*)(smem + AHI_OFF + off) = hi;
            *(uint2*)(smem + ALO_OFF + off) = lo;
        }
        __syncthreads();

        float acc[3][4];
#pragma unroll
        for (int nt = 0; nt < 3; nt++)
#pragma unroll
            for (int j = 0; j < 4; j++) acc[nt][j] = 0.f;

#pragma unroll
        for (int ks = 0; ks < 8; ks++) {
            const int k0 = ks * 16;
            uint32_t ah[4], al[4];
            uint32_t aoff = (uint32_t)((m0 + a_r) * ROWB + (k0 + a_kh * 8) * 2);
            ldsm_x4(ah[0], ah[1], ah[2], ah[3], sb + AHI_OFF + aoff);
            ldsm_x4(al[0], al[1], al[2], al[3], sb + ALO_OFF + aoff);
#pragma unroll
            for (int nt = 0; nt < 3; nt++) {
                if (nt >= NT) break;
                uint32_t boff = (uint32_t)((n0 + nt * 8 + b_r) * ROWB + (k0 + b_kh * 8) * 2);
                uint32_t bh0, bh1, bl0, bl1;
                ldsm_x2(bh0, bh1, sb + BHI_OFF + boff);
                ldsm_x2(bl0, bl1, sb + BLO_OFF + boff);
                mma_bf16(acc[nt][0], acc[nt][1], acc[nt][2], acc[nt][3],
                         ah[0], ah[1], ah[2], ah[3], bh0, bh1);
                mma_bf16(acc[nt][0], acc[nt][1], acc[nt][2], acc[nt][3],
                         ah[0], ah[1], ah[2], ah[3], bl0, bl1);
                mma_bf16(acc[nt][0], acc[nt][1], acc[nt][2], acc[nt][3],
                         al[0], al[1], al[2], al[3], bh0, bh1);
            }
        }
        __syncthreads();

        const int qr = lane >> 2, qc = (lane & 3) * 2;
        int r_a = row0 + m0 + qr, r_b = r_a + 8;
#pragma unroll
        for (int nt = 0; nt < 3; nt++) {
            if (nt >= NT) break;
            int col = n0 + nt * 8 + qc;
            if (r_a < M)
                *(float2*)(out + (size_t)r_a * NCLS + col) =
                    make_float2(acc[nt][0], acc[nt][1]);
            if (r_b < M)
                *(float2*)(out + (size_t)r_b * NCLS + col) =
                    make_float2(acc[nt][2], acc[nt][3]);
        }
    }
}

// ---------------- agg40a: l = dinv*(dinv*agg(u) + c), float2 lanes 0..19 ----------------
__global__ void __launch_bounds__(256)
agg40a_kernel() {
    int node = blockIdx.x * (blockDim.x >> 5) + (threadIdx.x >> 5);
    if (node >= NN) return;
    int lane = threadIdx.x & 31;
    const float* __restrict__ u = g_ta;
    const bool act = (lane < 20);

    int beg = g_rowptr[node], end = g_rowptr[node + 1];
    float a0 = 0.f, a1 = 0.f;
    int e = beg;
    for (; e + 8 <= end; e += 8) {
        int s[8];
#pragma unroll
        for (int j = 0; j < 8; j++) s[j] = __ldg(g_adj + e + j);
        float2 v[8];
#pragma unroll
        for (int j = 0; j < 8; j++)
            v[j] = act ? __ldg((const float2*)(u + (size_t)s[j] * NCLS) + lane)
                       : make_float2(0.f, 0.f);
#pragma unroll
        for (int j = 0; j < 8; j++) { a0 += v[j].x; a1 += v[j].y; }
    }
    for (; e < end; e++) {
        int s = __ldg(g_adj + e);
        if (act) {
            float2 v = __ldg((const float2*)(u + (size_t)s * NCLS) + lane);
            a0 += v.x; a1 += v.y;
        }
    }

    if (act) {
        float dn = g_dinv[node];
        float2 c = __ldg((const float2*)g_c + lane);
        float2 o;
        o.x = dn * (dn * a0 + c.x);
        o.y = dn * (dn * a1 + c.y);
        *((float2*)(g_l + (size_t)node * NCLS) + lane) = o;
    }
}

// ---------------- aggregation 40-wide + fused log_softmax (float2 lanes) ----------------
__global__ void __launch_bounds__(256)
agg40_lsm_kernel(const float* __restrict__ b3, float* __restrict__ out) {
    int node = blockIdx.x * (blockDim.x >> 5) + (threadIdx.x >> 5);
    if (node >= NN) return;
    int lane = threadIdx.x & 31;
    const bool act = (lane < 20);

    int beg = g_rowptr[node], end = g_rowptr[node + 1];
    float a0 = 0.f, a1 = 0.f;
    int e = beg;
    for (; e + 8 <= end; e += 8) {
        int s[8];
#pragma unroll
        for (int j = 0; j < 8; j++) s[j] = __ldg(g_adj + e + j);
        float2 v[8];
#pragma unroll
        for (int j = 0; j < 8; j++)
            v[j] = act ? __ldg((const float2*)(g_l + (size_t)s[j] * NCLS) + lane)
                       : make_float2(0.f, 0.f);
#pragma unroll
        for (int j = 0; j < 8; j++) { a0 += v[j].x; a1 += v[j].y; }
    }
    for (; e < end; e++) {
        int s = __ldg(g_adj + e);
        if (act) {
            float2 v = __ldg((const float2*)(g_l + (size_t)s * NCLS) + lane);
            a0 += v.x; a1 += v.y;
        }
    }

    float dn = g_dinv[node];
    float v0 = -1e30f, v1 = -1e30f;
    if (act) {
        float2 b = __ldg((const float2*)b3 + lane);
        v0 = a0 * dn + b.x;
        v1 = a1 * dn + b.y;
    }

    float m = fmaxf(v0, v1);
#pragma unroll
    for (int off = 16; off; off >>= 1)
        m = fmaxf(m, __shfl_xor_sync(0xffffffffu, m, off));
    float s = act ? (__expf(v0 - m) + __expf(v1 - m)) : 0.f;
#pragma unroll
    for (int off = 16; off; off >>= 1)
        s += __shfl_xor_sync(0xffffffffu, s, off);
    float L = __logf(s) + m;

    if (act)
        *((float2*)(out + (size_t)node * NCLS) + lane) =
            make_float2(v0 - L, v1 - L);
}

// ---------------- launch ----------------
extern "C" void kernel_launch(void* const* d_in, const int* in_sizes, int n_in,
                              void* d_out, int out_size) {
    const float* x  = (const float*)d_in[0];
    const int*   ei = (const int*)d_in[1];
    const float* W1 = (const float*)d_in[2];
    const float* b1 = (const float*)d_in[3];
    const float* W2 = (const float*)d_in[4];
    const float* b2 = (const float*)d_in[5];
    const float* W3 = (const float*)d_in[6];
    const float* b3 = (const float*)d_in[7];
    float* out = (float*)d_out;

    const int gN   = (NN + 255) / 256;
    const int gE   = (NE + 255) / 256;
    const int gET  = (ET + 255) / 256;
    const int gAgg = (NN + 7) / 8;

    const int SMEM128 = BHI_OFF + 2 * 128 * ROWB;  // 139264
    const int SMEM40  = BHI_OFF + 2 * 40 * ROWB;   //  91392
    cudaFuncSetAttribute(gemm1_kernel,
                         cudaFuncAttributeMaxDynamicSharedMemorySize, SMEM128);
    cudaFuncSetAttribute(fused2_kernel,
                         cudaFuncAttributeMaxDynamicSharedMemorySize, SMEM128);
    cudaFuncSetAttribute(gemm3_kernel,
                         cudaFuncAttributeMaxDynamicSharedMemorySize, SMEM40);

    // --- graph preprocessing ---
    init_deg_kernel<<<gN, 256>>>(ei);
    count_deg_kernel<<<gE, 256>>>(ei);
    scan1_kernel<<<NB_SCAN, SCAN_BLK>>>();
    scan3_kernel<<<NB_SCAN, 256>>>();
    fill_adj_kernel<<<gET, 256>>>(ei);

    // --- weight pre-pack + c = b2@W3 (single launch) ---
    pack_all_kernel<<<149, 256>>>(W1, W2, W3, b2);

    // --- layer 1: t1 = dinv*(x@W1) ---
    gemm1_kernel<<<148, 512, SMEM128>>>(x, NN);

    // --- layer 2 fused: t2 = dinv*( relu(dinv*agg(t1)+b1) @ W2 ) ---
    fused2_kernel<<<148, 512, SMEM128>>>(b1, NN);

    // --- layer 3 restructured (linearity): u = t2@W3, then 40-wide agg ---
    gemm3_kernel<<<296, 512, SMEM40>>>(NN);
    agg40a_kernel<<<gAgg, 256>>>();

    // --- final aggregation + log_softmax ---
    agg40_lsm_kernel<<<gAgg, 256>>>(b3, out);

    (void)in_sizes; (void)n_in; (void)out_size;
}

// round 16
// speedup vs baseline: 1.1570x; 1.1570x over previous
#include <cuda_runtime.h>
#include <cuda_bf16.h>
#include <math.h>
#include <stdint.h>

// Problem constants (fixed by the dataset)
#define NN 169343            // nodes
#define NE 1166243           // edges
#define ET (NE + NN)         // edges + self loops = 1335586
#define FDIM 128
#define NCLS 40
#define NTILES ((NN + 127) / 128)   // 1324

#define ROWS_PAD 136         // bf16 elements per padded row
#define ROWB 272             // bytes per padded row

// ---------------- device scratch (no cudaMalloc allowed) ----------------
__device__ int   g_is64;
__device__ int   g_deg[NN];
__device__ int   g_fill[NN];
__device__ int   g_rowptr[NN + 1];
__device__ int   g_bsum[256];
__device__ int   g_ctr;                   // fused2 tile work-queue counter
__device__ int   g_adj[ET];
__device__ float g_dinv[NN];
__device__ float g_c[NCLS];               // c = b2 @ W3
__device__ float g_ta[(size_t)NN * FDIM]; // t1; later reused as u = t2@W3 (40-wide)
__device__ float g_tb[(size_t)NN * FDIM]; // t2
__device__ float g_l[(size_t)NN * NCLS];  // layer-3 conv output l

// Pre-packed bf16 weight images ([n][k], padded rows, hi/lo split)
__device__ unsigned short g_Bh1[128 * ROWS_PAD], g_Bl1[128 * ROWS_PAD];
__device__ unsigned short g_Bh2[128 * ROWS_PAD], g_Bl2[128 * ROWS_PAD];
__device__ unsigned short g_Bh3[40 * ROWS_PAD],  g_Bl3[40 * ROWS_PAD];

// ---------------- PTX helpers (portable sm_80+ class only) ----------------
__device__ __forceinline__ uint32_t smem_u32(const void* p) {
    uint32_t a;
    asm("{ .reg .u64 t; cvta.to.shared.u64 t, %1; cvt.u32.u64 %0, t; }"
        : "=r"(a) : "l"(p));
    return a;
}

__device__ __forceinline__ void ldsm_x4(uint32_t& r0, uint32_t& r1,
                                        uint32_t& r2, uint32_t& r3, uint32_t addr) {
    asm volatile("ldmatrix.sync.aligned.m8n8.x4.shared.b16 {%0,%1,%2,%3}, [%4];"
                 : "=r"(r0), "=r"(r1), "=r"(r2), "=r"(r3) : "r"(addr));
}

__device__ __forceinline__ void ldsm_x2(uint32_t& r0, uint32_t& r1, uint32_t addr) {
    asm volatile("ldmatrix.sync.aligned.m8n8.x2.shared.b16 {%0,%1}, [%2];"
                 : "=r"(r0), "=r"(r1) : "r"(addr));
}

__device__ __forceinline__ void mma_bf16(float& d0, float& d1, float& d2, float& d3,
                                         uint32_t a0, uint32_t a1, uint32_t a2, uint32_t a3,
                                         uint32_t b0, uint32_t b1) {
    asm volatile(
        "mma.sync.aligned.m16n8k16.row.col.f32.bf16.bf16.f32 "
        "{%0,%1,%2,%3}, {%4,%5,%6,%7}, {%8,%9}, {%0,%1,%2,%3};"
        : "+f"(d0), "+f"(d1), "+f"(d2), "+f"(d3)
        : "r"(a0), "r"(a1), "r"(a2), "r"(a3), "r"(b0), "r"(b1));
}

// split fp32 float4 -> bf16 hi/lo packed uint2 pair
__device__ __forceinline__ void split4(const float4& v, uint2& hi, uint2& lo) {
    unsigned short h0, h1, h2, h3;
    asm("cvt.rn.bf16.f32 %0, %1;" : "=h"(h0) : "f"(v.x));
    asm("cvt.rn.bf16.f32 %0, %1;" : "=h"(h1) : "f"(v.y));
    asm("cvt.rn.bf16.f32 %0, %1;" : "=h"(h2) : "f"(v.z));
    asm("cvt.rn.bf16.f32 %0, %1;" : "=h"(h3) : "f"(v.w));
    float r0 = v.x - __uint_as_float((unsigned)h0 << 16);
    float r1 = v.y - __uint_as_float((unsigned)h1 << 16);
    float r2 = v.z - __uint_as_float((unsigned)h2 << 16);
    float r3 = v.w - __uint_as_float((unsigned)h3 << 16);
    hi.x = (uint32_t)h0 | ((uint32_t)h1 << 16);
    hi.y = (uint32_t)h2 | ((uint32_t)h3 << 16);
    asm("cvt.rn.bf16x2.f32 %0, %1, %2;" : "=r"(lo.x) : "f"(r1), "f"(r0));
    asm("cvt.rn.bf16x2.f32 %0, %1, %2;" : "=r"(lo.y) : "f"(r3), "f"(r2));
}

__device__ __forceinline__ int edge_src(const int* w, int e) {
    return g_is64 ? w[2 * e] : w[e];
}
__device__ __forceinline__ int edge_dst(const int* w, int e) {
    return g_is64 ? w[2 * (NE + e)] : w[NE + e];
}

// ---------------- preprocessing ----------------
__global__ void init_deg_kernel(const int* __restrict__ w) {
    int i = blockIdx.x * blockDim.x + threadIdx.x;
    if (i < NN) { g_deg[i] = 1; g_fill[i] = 0; }
    if (i == 0) g_ctr = 0;
    if (blockIdx.x == 0) {
        __shared__ int bad;
        if (threadIdx.x == 0) bad = 0;
        __syncthreads();
        for (int j = threadIdx.x; j < 1024; j += blockDim.x)
            if (w[2 * j + 1] != 0) atomicAdd(&bad, 1);
        __syncthreads();
        if (threadIdx.x == 0) g_is64 = (bad == 0) ? 1 : 0;
    }
}

__global__ void count_deg_kernel(const int* __restrict__ w) {
    int e = blockIdx.x * blockDim.x + threadIdx.x;
    if (e >= NE) return;
    atomicAdd(&g_deg[edge_dst(w, e)], 1);
}

#define SCAN_BLK 1024
#define NB_SCAN ((NN + SCAN_BLK - 1) / SCAN_BLK)   // 166

__global__ void scan1_kernel() {   // also computes dinv
    __shared__ int sh[SCAN_BLK];
    int i = blockIdx.x * SCAN_BLK + threadIdx.x;
    int v = (i < NN) ? g_deg[i] : 0;
    if (i < NN) g_dinv[i] = rsqrtf((float)v);
    sh[threadIdx.x] = v;
    __syncthreads();
    for (int off = 1; off < SCAN_BLK; off <<= 1) {
        int add = (threadIdx.x >= off) ? sh[threadIdx.x - off] : 0;
        __syncthreads();
        sh[threadIdx.x] += add;
        __syncthreads();
    }
    if (i < NN) g_rowptr[i + 1] = sh[threadIdx.x];
    if (threadIdx.x == SCAN_BLK - 1) g_bsum[blockIdx.x] = sh[threadIdx.x];
}

// merged scan2+scan3
__global__ void scan3_kernel() {
    __shared__ int sh[256];
    int t = threadIdx.x;
    sh[t] = (t < NB_SCAN) ? g_bsum[t] : 0;
    __syncthreads();
#pragma unroll
    for (int off = 1; off < 256; off <<= 1) {
        int add = (t >= off) ? sh[t - off] : 0;
        __syncthreads();
        sh[t] += add;
        __syncthreads();
    }
    int pref = (blockIdx.x == 0) ? 0 : sh[blockIdx.x - 1];
    if (blockIdx.x * SCAN_BLK + t == 0) g_rowptr[0] = 0;
#pragma unroll
    for (int rep = 0; rep < SCAN_BLK / 256; rep++) {
        int ii = blockIdx.x * SCAN_BLK + rep * 256 + t;
        if (ii < NN) g_rowptr[ii + 1] += pref;
    }
}

__global__ void fill_adj_kernel(const int* __restrict__ w) {
    int e = blockIdx.x * blockDim.x + threadIdx.x;
    if (e >= ET) return;
    int s, d;
    if (e < NE) { s = edge_src(w, e); d = edge_dst(w, e); }
    else        { s = d = e - NE; }
    int pos = g_rowptr[d] + atomicAdd(&g_fill[d], 1);
    g_adj[pos] = s;
}

// ---------------- weight pre-pack (all three + c = b2@W3, one launch) ----------------
__global__ void pack_all_kernel(const float* __restrict__ W1,
                                const float* __restrict__ W2,
                                const float* __restrict__ W3,
                                const float* __restrict__ b2) {
    int idx = blockIdx.x * blockDim.x + threadIdx.x;
    if (idx >= 37888 + NCLS) return;
    if (idx >= 37888) {
        int n = idx - 37888;
        float acc = 0.f;
        for (int k = 0; k < FDIM; k++)
            acc += b2[k] * W3[k * NCLS + n];
        g_c[n] = acc;
        return;
    }
    const float* W;
    unsigned short *bh, *bl;
    int Nout;
    if (idx < 16384)        { W = W1; bh = g_Bh1; bl = g_Bl1; Nout = 128; }
    else if (idx < 32768)   { idx -= 16384; W = W2; bh = g_Bh2; bl = g_Bl2; Nout = 128; }
    else                    { idx -= 32768; W = W3; bh = g_Bh3; bl = g_Bl3; Nout = 40; }
    int n = idx >> 7, k = idx & 127;
    float v = W[k * Nout + n];
    unsigned short h; asm("cvt.rn.bf16.f32 %0, %1;" : "=h"(h) : "f"(v));
    float hf = __uint_as_float(((unsigned)h) << 16);
    float rres = v - hf;
    unsigned short l; asm("cvt.rn.bf16.f32 %0, %1;" : "=h"(l) : "f"(rres));
    bh[n * ROWS_PAD + k] = h;
    bl[n * ROWS_PAD + k] = l;
}

// smem layout: AHI @0 (34816), ALO @34816, BHI @69632, BLO @69632+BBYTES
#define AHI_OFF 0
#define ALO_OFF 34816
#define BHI_OFF 69632

// ---------------- GEMM1: g_ta = dinv[row] * (x @ W1) ----------------
__global__ void __launch_bounds__(512, 1)
gemm1_kernel(const float* __restrict__ A, int M) {
    extern __shared__ __align__(16) char smem[];
    const int BLO_OFF = BHI_OFF + 128 * ROWB;
    const uint32_t sb = smem_u32(smem);
    const int tid = threadIdx.x, wid = tid >> 5, lane = tid & 31;

    for (int i = tid; i < (128 * ROWB) / 16; i += 512) {
        ((float4*)(smem + BHI_OFF))[i] = ((const float4*)g_Bh1)[i];
        ((float4*)(smem + BLO_OFF))[i] = ((const float4*)g_Bl1)[i];
    }

    const int m0 = (wid & 7) * 16;
    const int n0 = (wid >> 3) * 64;
    const int a_r = lane & 15, a_kh = lane >> 4;
    const int b_r = lane & 7,  b_kh = (lane >> 3) & 1;

    for (int tile = blockIdx.x; tile < NTILES; tile += gridDim.x) {
        const int row0 = tile * 128;

#pragma unroll
        for (int i = 0; i < 8; i++) {
            int idx = tid + i * 512;
            int r = idx >> 5, c4 = (idx & 31) << 2;
            int grow = row0 + r;
            float4 v = make_float4(0.f, 0.f, 0.f, 0.f);
            if (grow < M) v = *(const float4*)(A + (size_t)grow * FDIM + c4);
            uint2 hi, lo; split4(v, hi, lo);
            int off = r * ROWB + c4 * 2;
            *(uint2*)(smem + AHI_OFF + off) = hi;
            *(uint2*)(smem + ALO_OFF + off) = lo;
        }
        __syncthreads();

        float acc[8][4];
#pragma unroll
        for (int nt = 0; nt < 8; nt++)
#pragma unroll
            for (int j = 0; j < 4; j++) acc[nt][j] = 0.f;

#pragma unroll
        for (int ks = 0; ks < 8; ks++) {
            const int k0 = ks * 16;
            uint32_t ah[4], al[4];
            uint32_t aoff = (uint32_t)((m0 + a_r) * ROWB + (k0 + a_kh * 8) * 2);
            ldsm_x4(ah[0], ah[1], ah[2], ah[3], sb + AHI_OFF + aoff);
            ldsm_x4(al[0], al[1], al[2], al[3], sb + ALO_OFF + aoff);
#pragma unroll
            for (int nt = 0; nt < 8; nt++) {
                uint32_t boff = (uint32_t)((n0 + nt * 8 + b_r) * ROWB + (k0 + b_kh * 8) * 2);
                uint32_t bh0, bh1, bl0, bl1;
                ldsm_x2(bh0, bh1, sb + BHI_OFF + boff);
                ldsm_x2(bl0, bl1, sb + BLO_OFF + boff);
                mma_bf16(acc[nt][0], acc[nt][1], acc[nt][2], acc[nt][3],
                         ah[0], ah[1], ah[2], ah[3], bh0, bh1);
                mma_bf16(acc[nt][0], acc[nt][1], acc[nt][2], acc[nt][3],
                         ah[0], ah[1], ah[2], ah[3], bl0, bl1);
                mma_bf16(acc[nt][0], acc[nt][1], acc[nt][2], acc[nt][3],
                         al[0], al[1], al[2], al[3], bh0, bh1);
            }
        }
        __syncthreads();

        const int qr = lane >> 2, qc = (lane & 3) * 2;
        int r_a = row0 + m0 + qr, r_b = r_a + 8;
        float dna = (r_a < M) ? g_dinv[r_a] : 0.f;
        float dnb = (r_b < M) ? g_dinv[r_b] : 0.f;
#pragma unroll
        for (int nt = 0; nt < 8; nt++) {
            int col = n0 + nt * 8 + qc;
            if (r_a < M)
                *(float2*)(g_ta + (size_t)r_a * FDIM + col) =
                    make_float2(acc[nt][0] * dna, acc[nt][1] * dna);
            if (r_b < M)
                *(float2*)(g_ta + (size_t)r_b * FDIM + col) =
                    make_float2(acc[nt][2] * dnb, acc[nt][3] * dnb);
        }
    }
}

// ---------------- fused2: t2 = dinv*( relu(dinv*agg(t1)+b1) @ W2 ) ----------------
// R14-proven body; tiles are claimed from a global work queue (one atomic
// per tile) to absorb cross-tile degree skew. Output independent of
// assignment; counter reset in init_deg each call.
__global__ void __launch_bounds__(512, 1)
fused2_kernel(const float* __restrict__ bias, int M) {
    extern __shared__ __align__(16) char smem[];
    const int BBYTES = 128 * ROWB;
    const int BLO_OFF = BHI_OFF + BBYTES;
    const uint32_t sb = smem_u32(smem);
    const int tid = threadIdx.x, wid = tid >> 5, lane = tid & 31;

    const float* __restrict__ src = g_ta;
    float* __restrict__ out = g_tb;

    for (int i = tid; i < BBYTES / 16; i += 512) {
        ((float4*)(smem + BHI_OFF))[i] = ((const float4*)g_Bh2)[i];
        ((float4*)(smem + BLO_OFF))[i] = ((const float4*)g_Bl2)[i];
    }

    const int m0 = (wid & 7) * 16;
    const int n0 = (wid >> 3) * 64;
    const int a_r = lane & 15, a_kh = lane >> 4;
    const int b_r = lane & 7,  b_kh = (lane >> 3) & 1;

    const float4 bv = __ldg((const float4*)bias + lane);

    __shared__ int s_tile;
    for (;;) {
        if (tid == 0) s_tile = atomicAdd(&g_ctr, 1);
        __syncthreads();
        const int tile = s_tile;
        if (tile >= NTILES) break;
        const int row0 = tile * 128;

        // ---- gather phase: warp w -> rows w*8 .. w*8+7 (8-edge unrolled) ----
#pragma unroll
        for (int r8 = 0; r8 < 8; r8++) {
            int lr = wid * 8 + r8;
            int node = row0 + lr;
            float4 acc = make_float4(0.f, 0.f, 0.f, 0.f);
            if (node < M) {
                int beg = g_rowptr[node], end = g_rowptr[node + 1];
                int e = beg;
                for (; e + 8 <= end; e += 8) {
                    int s[8];
#pragma unroll
                    for (int j = 0; j < 8; j++) s[j] = __ldg(g_adj + e + j);
                    float4 v[8];
#pragma unroll
                    for (int j = 0; j < 8; j++)
                        v[j] = __ldg((const float4*)(src + (size_t)s[j] * FDIM) + lane);
#pragma unroll
                    for (int j = 0; j < 8; j++) {
                        acc.x += v[j].x; acc.y += v[j].y;
                        acc.z += v[j].z; acc.w += v[j].w;
                    }
                }
                for (; e + 2 <= end; e += 2) {
                    int s0 = __ldg(g_adj + e), s1 = __ldg(g_adj + e + 1);
                    float4 v0 = __ldg((const float4*)(src + (size_t)s0 * FDIM) + lane);
                    float4 v1 = __ldg((const float4*)(src + (size_t)s1 * FDIM) + lane);
                    acc.x += v0.x + v1.x; acc.y += v0.y + v1.y;
                    acc.z += v0.z + v1.z; acc.w += v0.w + v1.w;
                }
                if (e < end) {
                    int s0 = __ldg(g_adj + e);
                    float4 v0 = __ldg((const float4*)(src + (size_t)s0 * FDIM) + lane);
                    acc.x += v0.x; acc.y += v0.y; acc.z += v0.z; acc.w += v0.w;
                }
                float dn = g_dinv[node];
                acc.x = fmaf(acc.x, dn, bv.x);
                acc.y = fmaf(acc.y, dn, bv.y);
                acc.z = fmaf(acc.z, dn, bv.z);
                acc.w = fmaf(acc.w, dn, bv.w);
                acc.x = fmaxf(acc.x, 0.f); acc.y = fmaxf(acc.y, 0.f);
                acc.z = fmaxf(acc.z, 0.f); acc.w = fmaxf(acc.w, 0.f);
            }
            uint2 hi, lo; split4(acc, hi, lo);
            int off = lr * ROWB + lane * 8;
            *(uint2*)(smem + AHI_OFF + off) = hi;
            *(uint2*)(smem + ALO_OFF + off) = lo;
        }
        __syncthreads();

        // ---- MMA phase ----
        float acc[8][4];
#pragma unroll
        for (int nt = 0; nt < 8; nt++)
#pragma unroll
            for (int j = 0; j < 4; j++) acc[nt][j] = 0.f;

#pragma unroll
        for (int ks = 0; ks < 8; ks++) {
            const int k0 = ks * 16;
            uint32_t ah[4], al[4];
            uint32_t aoff = (uint32_t)((m0 + a_r) * ROWB + (k0 + a_kh * 8) * 2);
            ldsm_x4(ah[0], ah[1], ah[2], ah[3], sb + AHI_OFF + aoff);
            ldsm_x4(al[0], al[1], al[2], al[3], sb + ALO_OFF + aoff);
#pragma unroll
            for (int nt = 0; nt < 8; nt++) {
                uint32_t boff = (uint32_t)((n0 + nt * 8 + b_r) * ROWB + (k0 + b_kh * 8) * 2);
                uint32_t bh0, bh1, bl0, bl1;
                ldsm_x2(bh0, bh1, sb + BHI_OFF + boff);
                ldsm_x2(bl0, bl1, sb + BLO_OFF + boff);
                mma_bf16(acc[nt][0], acc[nt][1], acc[nt][2], acc[nt][3],
                         ah[0], ah[1], ah[2], ah[3], bh0, bh1);
                mma_bf16(acc[nt][0], acc[nt][1], acc[nt][2], acc[nt][3],
                         ah[0], ah[1], ah[2], ah[3], bl0, bl1);
                mma_bf16(acc[nt][0], acc[nt][1], acc[nt][2], acc[nt][3],
                         al[0], al[1], al[2], al[3], bh0, bh1);
            }
        }
        __syncthreads();

        const int qr = lane >> 2, qc = (lane & 3) * 2;
        int r_a = row0 + m0 + qr, r_b = r_a + 8;
        float dna = (r_a < M) ? g_dinv[r_a] : 0.f;
        float dnb = (r_b < M) ? g_dinv[r_b] : 0.f;
#pragma unroll
        for (int nt = 0; nt < 8; nt++) {
            int col = n0 + nt * 8 + qc;
            if (r_a < M)
                *(float2*)(out + (size_t)r_a * FDIM + col) =
                    make_float2(acc[nt][0] * dna, acc[nt][1] * dna);
            if (r_b < M)
                *(float2*)(out + (size_t)r_b * FDIM + col) =
                    make_float2(acc[nt][2] * dnb, acc[nt][3] * dnb);
        }
    }
}

// ---------------- GEMM3: u = t2 @ W3 (plain, 40-wide, u stored in g_ta) ----------------
__global__ void __launch_bounds__(512, 2)
gemm3_kernel(int M) {
    extern __shared__ __align__(16) char smem[];
    const int BBYTES = 40 * ROWB;
    const int BLO_OFF = BHI_OFF + BBYTES;
    const uint32_t sb = smem_u32(smem);
    const int tid = threadIdx.x, wid = tid >> 5, lane = tid & 31;

    const float* __restrict__ A = g_tb;
    float* __restrict__ out = g_ta;   // u, row stride NCLS

    for (int i = tid; i < BBYTES / 16; i += 512) {
        ((float4*)(smem + BHI_OFF))[i] = ((const float4*)g_Bh3)[i];
        ((float4*)(smem + BLO_OFF))[i] = ((const float4*)g_Bl3)[i];
    }

    const int m0 = (wid & 7) * 16;
    const int nhalf = wid >> 3;
    const int n0 = nhalf * 24;
    const int NT = nhalf ? 2 : 3;
    const int a_r = lane & 15, a_kh = lane >> 4;
    const int b_r = lane & 7,  b_kh = (lane >> 3) & 1;

    for (int tile = blockIdx.x; tile < NTILES; tile += gridDim.x) {
        const int row0 = tile * 128;

#pragma unroll
        for (int i = 0; i < 8; i++) {
            int idx = tid + i * 512;
            int r = idx >> 5, c4 = (idx & 31) << 2;
            int grow = row0 + r;
            float4 v = make_float4(0.f, 0.f, 0.f, 0.f);
            if (grow < M) v = *(const float4*)(A + (size_t)grow * FDIM + c4);
            uint2 hi, lo; split4(v, hi, lo);
            int off = r * ROWB + c4 * 2;
            *(uint2*)(smem + AHI_OFF + off) = hi;
            *(uint2*)(smem + ALO_OFF + off) = lo;
        }
        __syncthreads();

        float acc[3][4];
#pragma unroll
        for (int nt = 0; nt < 3; nt++)
#pragma unroll
            for (int j = 0; j < 4; j++) acc[nt][j] = 0.f;

#pragma unroll
        for (int ks = 0; ks < 8; ks++) {
            const int k0 = ks * 16;
            uint32_t ah[4], al[4];
            uint32_t aoff = (uint32_t)((m0 + a_r) * ROWB + (k0 + a_kh * 8) * 2);
            ldsm_x4(ah[0], ah[1], ah[2], ah[3], sb + AHI_OFF + aoff);
            ldsm_x4(al[0], al[1], al[2], al[3], sb + ALO_OFF + aoff);
#pragma unroll
            for (int nt = 0; nt < 3; nt++) {
                if (nt >= NT) break;
                uint32_t boff = (uint32_t)((n0 + nt * 8 + b_r) * ROWB + (k0 + b_kh * 8) * 2);
                uint32_t bh0, bh1, bl0, bl1;
                ldsm_x2(bh0, bh1, sb + BHI_OFF + boff);
                ldsm_x2(bl0, bl1, sb + BLO_OFF + boff);
                mma_bf16(acc[nt][0], acc[nt][1], acc[nt][2], acc[nt][3],
                         ah[0], ah[1], ah[2], ah[3], bh0, bh1);
                mma_bf16(acc[nt][0], acc[nt][1], acc[nt][2], acc[nt][3],
                         ah[0], ah[1], ah[2], ah[3], bl0, bl1);
                mma_bf16(acc[nt][0], acc[nt][1], acc[nt][2], acc[nt][3],
                         al[0], al[1], al[2], al[3], bh0, bh1);
            }
        }
        __syncthreads();

        const int qr = lane >> 2, qc = (lane & 3) * 2;
        int r_a = row0 + m0 + qr, r_b = r_a + 8;
#pragma unroll
        for (int nt = 0; nt < 3; nt++) {
            if (nt >= NT) break;
            int col = n0 + nt * 8 + qc;
            if (r_a < M)
                *(float2*)(out + (size_t)r_a * NCLS + col) =
                    make_float2(acc[nt][0], acc[nt][1]);
            if (r_b < M)
                *(float2*)(out + (size_t)r_b * NCLS + col) =
                    make_float2(acc[nt][2], acc[nt][3]);
        }
    }
}

// ---------------- agg40a: l = dinv*(dinv*agg(u) + c), float2 lanes 0..19 ----------------
__global__ void __launch_bounds__(256)
agg40a_kernel() {
    int node = blockIdx.x * (blockDim.x >> 5) + (threadIdx.x >> 5);
    if (node >= NN) return;
    int lane = threadIdx.x & 31;
    const float* __restrict__ u = g_ta;
    const bool act = (lane < 20);

    int beg = g_rowptr[node], end = g_rowptr[node + 1];
    float a0 = 0.f, a1 = 0.f;
    int e = beg;
    for (; e + 8 <= end; e += 8) {
        int s[8];
#pragma unroll
        for (int j = 0; j < 8; j++) s[j] = __ldg(g_adj + e + j);
        float2 v[8];
#pragma unroll
        for (int j = 0; j < 8; j++)
            v[j] = act ? __ldg((const float2*)(u + (size_t)s[j] * NCLS) + lane)
                       : make_float2(0.f, 0.f);
#pragma unroll
        for (int j = 0; j < 8; j++) { a0 += v[j].x; a1 += v[j].y; }
    }
    for (; e < end; e++) {
        int s = __ldg(g_adj + e);
        if (act) {
            float2 v = __ldg((const float2*)(u + (size_t)s * NCLS) + lane);
            a0 += v.x; a1 += v.y;
        }
    }

    if (act) {
        float dn = g_dinv[node];
        float2 c = __ldg((const float2*)g_c + lane);
        float2 o;
        o.x = dn * (dn * a0 + c.x);
        o.y = dn * (dn * a1 + c.y);
        *((float2*)(g_l + (size_t)node * NCLS) + lane) = o;
    }
}

// ---------------- aggregation 40-wide + fused log_softmax (float2 lanes) ----------------
__global__ void __launch_bounds__(256)
agg40_lsm_kernel(const float* __restrict__ b3, float* __restrict__ out) {
    int node = blockIdx.x * (blockDim.x >> 5) + (threadIdx.x >> 5);
    if (node >= NN) return;
    int lane = threadIdx.x & 31;
    const bool act = (lane < 20);

    int beg = g_rowptr[node], end = g_rowptr[node + 1];
    float a0 = 0.f, a1 = 0.f;
    int e = beg;
    for (; e + 8 <= end; e += 8) {
        int s[8];
#pragma unroll
        for (int j = 0; j < 8; j++) s[j] = __ldg(g_adj + e + j);
        float2 v[8];
#pragma unroll
        for (int j = 0; j < 8; j++)
            v[j] = act ? __ldg((const float2*)(g_l + (size_t)s[j] * NCLS) + lane)
                       : make_float2(0.f, 0.f);
#pragma unroll
        for (int j = 0; j < 8; j++) { a0 += v[j].x; a1 += v[j].y; }
    }
    for (; e < end; e++) {
        int s = __ldg(g_adj + e);
        if (act) {
            float2 v = __ldg((const float2*)(g_l + (size_t)s * NCLS) + lane);
            a0 += v.x; a1 += v.y;
        }
    }

    float dn = g_dinv[node];
    float v0 = -1e30f, v1 = -1e30f;
    if (act) {
        float2 b = __ldg((const float2*)b3 + lane);
        v0 = a0 * dn + b.x;
        v1 = a1 * dn + b.y;
    }

    float m = fmaxf(v0, v1);
#pragma unroll
    for (int off = 16; off; off >>= 1)
        m = fmaxf(m, __shfl_xor_sync(0xffffffffu, m, off));
    float s = act ? (__expf(v0 - m) + __expf(v1 - m)) : 0.f;
#pragma unroll
    for (int off = 16; off; off >>= 1)
        s += __shfl_xor_sync(0xffffffffu, s, off);
    float L = __logf(s) + m;

    if (act)
        *((float2*)(out + (size_t)node * NCLS) + lane) =
            make_float2(v0 - L, v1 - L);
}

// ---------------- launch ----------------
extern "C" void kernel_launch(void* const* d_in, const int* in_sizes, int n_in,
                              void* d_out, int out_size) {
    const float* x  = (const float*)d_in[0];
    const int*   ei = (const int*)d_in[1];
    const float* W1 = (const float*)d_in[2];
    const float* b1 = (const float*)d_in[3];
    const float* W2 = (const float*)d_in[4];
    const float* b2 = (const float*)d_in[5];
    const float* W3 = (const float*)d_in[6];
    const float* b3 = (const float*)d_in[7];
    float* out = (float*)d_out;

    const int gN   = (NN + 255) / 256;
    const int gE   = (NE + 255) / 256;
    const int gET  = (ET + 255) / 256;
    const int gAgg = (NN + 7) / 8;

    const int SMEM128 = BHI_OFF + 2 * 128 * ROWB;  // 139264
    const int SMEM40  = BHI_OFF + 2 * 40 * ROWB;   //  91392
    cudaFuncSetAttribute(gemm1_kernel,
                         cudaFuncAttributeMaxDynamicSharedMemorySize, SMEM128);
    cudaFuncSetAttribute(fused2_kernel,
                         cudaFuncAttributeMaxDynamicSharedMemorySize, SMEM128);
    cudaFuncSetAttribute(gemm3_kernel,
                         cudaFuncAttributeMaxDynamicSharedMemorySize, SMEM40);

    // --- graph preprocessing ---
    init_deg_kernel<<<gN, 256>>>(ei);
    count_deg_kernel<<<gE, 256>>>(ei);
    scan1_kernel<<<NB_SCAN, SCAN_BLK>>>();
    scan3_kernel<<<NB_SCAN, 256>>>();
    fill_adj_kernel<<<gET, 256>>>(ei);

    // --- weight pre-pack + c = b2@W3 (single launch) ---
    pack_all_kernel<<<149, 256>>>(W1, W2, W3, b2);

    // --- layer 1: t1 = dinv*(x@W1) ---
    gemm1_kernel<<<148, 512, SMEM128>>>(x, NN);

    // --- layer 2 fused: t2 = dinv*( relu(dinv*agg(t1)+b1) @ W2 ) ---
    fused2_kernel<<<148, 512, SMEM128>>>(b1, NN);

    // --- layer 3 restructured (linearity): u = t2@W3, then 40-wide agg ---
    gemm3_kernel<<<296, 512, SMEM40>>>(NN);
    agg40a_kernel<<<gAgg, 256>>>();

    // --- final aggregation + log_softmax ---
    agg40_lsm_kernel<<<gAgg, 256>>>(b3, out);

    (void)in_sizes; (void)n_in; (void)out_size;
}

// round 17
// speedup vs baseline: 1.2841x; 1.1099x over previous
#include <cuda_runtime.h>
#include <cuda_bf16.h>
#include <math.h>
#include <stdint.h>

// Problem constants (fixed by the dataset)
#define NN 169343            // nodes
#define NE 1166243           // edges
#define ET (NE + NN)         // edges + self loops = 1335586
#define FDIM 128
#define NCLS 40
#define NTILES ((NN + 127) / 128)    // 1324 (128-row tiles)
#define NTILES64 ((NN + 63) / 64)    // 2647 (64-row tiles)

#define ROWS_PAD 136         // bf16 elements per padded row
#define ROWB 272             // bytes per padded row

// ---------------- device scratch (no cudaMalloc allowed) ----------------
__device__ int   g_is64;
__device__ int   g_deg[NN];
__device__ int   g_fill[NN];
__device__ int   g_rowptr[NN + 1];
__device__ int   g_bsum[256];
__device__ int   g_adj[ET];
__device__ float g_dinv[NN];
__device__ float g_c[NCLS];               // c = b2 @ W3
__device__ float g_ta[(size_t)NN * FDIM]; // t1; later reused as u = t2@W3 (40-wide)
__device__ float g_tb[(size_t)NN * FDIM]; // t2
__device__ float g_l[(size_t)NN * NCLS];  // layer-3 conv output l

// Pre-packed bf16 weight images ([n][k], padded rows, hi/lo split)
__device__ unsigned short g_Bh1[128 * ROWS_PAD], g_Bl1[128 * ROWS_PAD];
__device__ unsigned short g_Bh2[128 * ROWS_PAD], g_Bl2[128 * ROWS_PAD];
__device__ unsigned short g_Bh3[40 * ROWS_PAD],  g_Bl3[40 * ROWS_PAD];

// ---------------- PTX helpers (portable sm_80+ class only) ----------------
__device__ __forceinline__ uint32_t smem_u32(const void* p) {
    uint32_t a;
    asm("{ .reg .u64 t; cvta.to.shared.u64 t, %1; cvt.u32.u64 %0, t; }"
        : "=r"(a) : "l"(p));
    return a;
}

__device__ __forceinline__ void ldsm_x4(uint32_t& r0, uint32_t& r1,
                                        uint32_t& r2, uint32_t& r3, uint32_t addr) {
    asm volatile("ldmatrix.sync.aligned.m8n8.x4.shared.b16 {%0,%1,%2,%3}, [%4];"
                 : "=r"(r0), "=r"(r1), "=r"(r2), "=r"(r3) : "r"(addr));
}

__device__ __forceinline__ void ldsm_x2(uint32_t& r0, uint32_t& r1, uint32_t addr) {
    asm volatile("ldmatrix.sync.aligned.m8n8.x2.shared.b16 {%0,%1}, [%2];"
                 : "=r"(r0), "=r"(r1) : "r"(addr));
}

__device__ __forceinline__ void mma_bf16(float& d0, float& d1, float& d2, float& d3,
                                         uint32_t a0, uint32_t a1, uint32_t a2, uint32_t a3,
                                         uint32_t b0, uint32_t b1) {
    asm volatile(
        "mma.sync.aligned.m16n8k16.row.col.f32.bf16.bf16.f32 "
        "{%0,%1,%2,%3}, {%4,%5,%6,%7}, {%8,%9}, {%0,%1,%2,%3};"
        : "+f"(d0), "+f"(d1), "+f"(d2), "+f"(d3)
        : "r"(a0), "r"(a1), "r"(a2), "r"(a3), "r"(b0), "r"(b1));
}

// split fp32 float4 -> bf16 hi/lo packed uint2 pair
__device__ __forceinline__ void split4(const float4& v, uint2& hi, uint2& lo) {
    unsigned short h0, h1, h2, h3;
    asm("cvt.rn.bf16.f32 %0, %1;" : "=h"(h0) : "f"(v.x));
    asm("cvt.rn.bf16.f32 %0, %1;" : "=h"(h1) : "f"(v.y));
    asm("cvt.rn.bf16.f32 %0, %1;" : "=h"(h2) : "f"(v.z));
    asm("cvt.rn.bf16.f32 %0, %1;" : "=h"(h3) : "f"(v.w));
    float r0 = v.x - __uint_as_float((unsigned)h0 << 16);
    float r1 = v.y - __uint_as_float((unsigned)h1 << 16);
    float r2 = v.z - __uint_as_float((unsigned)h2 << 16);
    float r3 = v.w - __uint_as_float((unsigned)h3 << 16);
    hi.x = (uint32_t)h0 | ((uint32_t)h1 << 16);
    hi.y = (uint32_t)h2 | ((uint32_t)h3 << 16);
    asm("cvt.rn.bf16x2.f32 %0, %1, %2;" : "=r"(lo.x) : "f"(r1), "f"(r0));
    asm("cvt.rn.bf16x2.f32 %0, %1, %2;" : "=r"(lo.y) : "f"(r3), "f"(r2));
}

__device__ __forceinline__ int edge_src(const int* w, int e) {
    return g_is64 ? w[2 * e] : w[e];
}
__device__ __forceinline__ int edge_dst(const int* w, int e) {
    return g_is64 ? w[2 * (NE + e)] : w[NE + e];
}

// ---------------- preprocessing ----------------
__global__ void init_deg_kernel(const int* __restrict__ w) {
    int i = blockIdx.x * blockDim.x + threadIdx.x;
    if (i < NN) { g_deg[i] = 1; g_fill[i] = 0; }
    if (blockIdx.x == 0) {
        __shared__ int bad;
        if (threadIdx.x == 0) bad = 0;
        __syncthreads();
        for (int j = threadIdx.x; j < 1024; j += blockDim.x)
            if (w[2 * j + 1] != 0) atomicAdd(&bad, 1);
        __syncthreads();
        if (threadIdx.x == 0) g_is64 = (bad == 0) ? 1 : 0;
    }
}

__global__ void count_deg_kernel(const int* __restrict__ w) {
    int e = blockIdx.x * blockDim.x + threadIdx.x;
    if (e >= NE) return;
    atomicAdd(&g_deg[edge_dst(w, e)], 1);
}

#define SCAN_BLK 1024
#define NB_SCAN ((NN + SCAN_BLK - 1) / SCAN_BLK)   // 166

__global__ void scan1_kernel() {   // also computes dinv
    __shared__ int sh[SCAN_BLK];
    int i = blockIdx.x * SCAN_BLK + threadIdx.x;
    int v = (i < NN) ? g_deg[i] : 0;
    if (i < NN) g_dinv[i] = rsqrtf((float)v);
    sh[threadIdx.x] = v;
    __syncthreads();
    for (int off = 1; off < SCAN_BLK; off <<= 1) {
        int add = (threadIdx.x >= off) ? sh[threadIdx.x - off] : 0;
        __syncthreads();
        sh[threadIdx.x] += add;
        __syncthreads();
    }
    if (i < NN) g_rowptr[i + 1] = sh[threadIdx.x];
    if (threadIdx.x == SCAN_BLK - 1) g_bsum[blockIdx.x] = sh[threadIdx.x];
}

// merged scan2+scan3
__global__ void scan3_kernel() {
    __shared__ int sh[256];
    int t = threadIdx.x;
    sh[t] = (t < NB_SCAN) ? g_bsum[t] : 0;
    __syncthreads();
#pragma unroll
    for (int off = 1; off < 256; off <<= 1) {
        int add = (t >= off) ? sh[t - off] : 0;
        __syncthreads();
        sh[t] += add;
        __syncthreads();
    }
    int pref = (blockIdx.x == 0) ? 0 : sh[blockIdx.x - 1];
    if (blockIdx.x * SCAN_BLK + t == 0) g_rowptr[0] = 0;
#pragma unroll
    for (int rep = 0; rep < SCAN_BLK / 256; rep++) {
        int ii = blockIdx.x * SCAN_BLK + rep * 256 + t;
        if (ii < NN) g_rowptr[ii + 1] += pref;
    }
}

__global__ void fill_adj_kernel(const int* __restrict__ w) {
    int e = blockIdx.x * blockDim.x + threadIdx.x;
    if (e >= ET) return;
    int s, d;
    if (e < NE) { s = edge_src(w, e); d = edge_dst(w, e); }
    else        { s = d = e - NE; }
    int pos = g_rowptr[d] + atomicAdd(&g_fill[d], 1);
    g_adj[pos] = s;
}

// ---------------- weight pre-pack (all three + c = b2@W3, one launch) ----------------
__global__ void pack_all_kernel(const float* __restrict__ W1,
                                const float* __restrict__ W2,
                                const float* __restrict__ W3,
                                const float* __restrict__ b2) {
    int idx = blockIdx.x * blockDim.x + threadIdx.x;
    if (idx >= 37888 + NCLS) return;
    if (idx >= 37888) {
        int n = idx - 37888;
        float acc = 0.f;
        for (int k = 0; k < FDIM; k++)
            acc += b2[k] * W3[k * NCLS + n];
        g_c[n] = acc;
        return;
    }
    const float* W;
    unsigned short *bh, *bl;
    int Nout;
    if (idx < 16384)        { W = W1; bh = g_Bh1; bl = g_Bl1; Nout = 128; }
    else if (idx < 32768)   { idx -= 16384; W = W2; bh = g_Bh2; bl = g_Bl2; Nout = 128; }
    else                    { idx -= 32768; W = W3; bh = g_Bh3; bl = g_Bl3; Nout = 40; }
    int n = idx >> 7, k = idx & 127;
    float v = W[k * Nout + n];
    unsigned short h; asm("cvt.rn.bf16.f32 %0, %1;" : "=h"(h) : "f"(v));
    float hf = __uint_as_float(((unsigned)h) << 16);
    float rres = v - hf;
    unsigned short l; asm("cvt.rn.bf16.f32 %0, %1;" : "=h"(l) : "f"(rres));
    bh[n * ROWS_PAD + k] = h;
    bl[n * ROWS_PAD + k] = l;
}

// smem layout (128-row kernels): AHI @0, ALO @34816, BHI @69632, BLO @69632+BBYTES
#define AHI_OFF 0
#define ALO_OFF 34816
#define BHI_OFF 69632

// ---------------- GEMM1: g_ta = dinv[row] * (x @ W1) ----------------
__global__ void __launch_bounds__(512, 1)
gemm1_kernel(const float* __restrict__ A, int M) {
    extern __shared__ __align__(16) char smem[];
    const int BLO_OFF = BHI_OFF + 128 * ROWB;
    const uint32_t sb = smem_u32(smem);
    const int tid = threadIdx.x, wid = tid >> 5, lane = tid & 31;

    for (int i = tid; i < (128 * ROWB) / 16; i += 512) {
        ((float4*)(smem + BHI_OFF))[i] = ((const float4*)g_Bh1)[i];
        ((float4*)(smem + BLO_OFF))[i] = ((const float4*)g_Bl1)[i];
    }

    const int m0 = (wid & 7) * 16;
    const int n0 = (wid >> 3) * 64;
    const int a_r = lane & 15, a_kh = lane >> 4;
    const int b_r = lane & 7,  b_kh = (lane >> 3) & 1;

    for (int tile = blockIdx.x; tile < NTILES; tile += gridDim.x) {
        const int row0 = tile * 128;

#pragma unroll
        for (int i = 0; i < 8; i++) {
            int idx = tid + i * 512;
            int r = idx >> 5, c4 = (idx & 31) << 2;
            int grow = row0 + r;
            float4 v = make_float4(0.f, 0.f, 0.f, 0.f);
            if (grow < M) v = *(const float4*)(A + (size_t)grow * FDIM + c4);
            uint2 hi, lo; split4(v, hi, lo);
            int off = r * ROWB + c4 * 2;
            *(uint2*)(smem + AHI_OFF + off) = hi;
            *(uint2*)(smem + ALO_OFF + off) = lo;
        }
        __syncthreads();

        float acc[8][4];
#pragma unroll
        for (int nt = 0; nt < 8; nt++)
#pragma unroll
            for (int j = 0; j < 4; j++) acc[nt][j] = 0.f;

#pragma unroll
        for (int ks = 0; ks < 8; ks++) {
            const int k0 = ks * 16;
            uint32_t ah[4], al[4];
            uint32_t aoff = (uint32_t)((m0 + a_r) * ROWB + (k0 + a_kh * 8) * 2);
            ldsm_x4(ah[0], ah[1], ah[2], ah[3], sb + AHI_OFF + aoff);
            ldsm_x4(al[0], al[1], al[2], al[3], sb + ALO_OFF + aoff);
#pragma unroll
            for (int nt = 0; nt < 8; nt++) {
                uint32_t boff = (uint32_t)((n0 + nt * 8 + b_r) * ROWB + (k0 + b_kh * 8) * 2);
                uint32_t bh0, bh1, bl0, bl1;
                ldsm_x2(bh0, bh1, sb + BHI_OFF + boff);
                ldsm_x2(bl0, bl1, sb + BLO_OFF + boff);
                mma_bf16(acc[nt][0], acc[nt][1], acc[nt][2], acc[nt][3],
                         ah[0], ah[1], ah[2], ah[3], bh0, bh1);
                mma_bf16(acc[nt][0], acc[nt][1], acc[nt][2], acc[nt][3],
                         ah[0], ah[1], ah[2], ah[3], bl0, bl1);
                mma_bf16(acc[nt][0], acc[nt][1], acc[nt][2], acc[nt][3],
                         al[0], al[1], al[2], al[3], bh0, bh1);
            }
        }
        __syncthreads();

        const int qr = lane >> 2, qc = (lane & 3) * 2;
        int r_a = row0 + m0 + qr, r_b = r_a + 8;
        float dna = (r_a < M) ? g_dinv[r_a] : 0.f;
        float dnb = (r_b < M) ? g_dinv[r_b] : 0.f;
#pragma unroll
        for (int nt = 0; nt < 8; nt++) {
            int col = n0 + nt * 8 + qc;
            if (r_a < M)
                *(float2*)(g_ta + (size_t)r_a * FDIM + col) =
                    make_float2(acc[nt][0] * dna, acc[nt][1] * dna);
            if (r_b < M)
                *(float2*)(g_ta + (size_t)r_b * FDIM + col) =
                    make_float2(acc[nt][2] * dnb, acc[nt][3] * dnb);
        }
    }
}

// ---------------- fused2: t2 = dinv*( relu(dinv*agg(t1)+b1) @ W2 ) ----------------
// 64-row M tiles, 2 CTAs/SM. smem: AHI @0 (17408), ALO @17408, BHI @34816,
// BLO @69632. 16 warps: 4 m-tiles x 4 n-groups (32 cols). Gather: 4 rows/warp,
// same proven 8-edge-unrolled inner loop as R14.
#define F2_AHI 0
#define F2_ALO 17408
#define F2_BHI 34816
#define F2_BLO 69632
#define F2_SMEM 104448

__global__ void __launch_bounds__(512, 2)
fused2_kernel(const float* __restrict__ bias, int M) {
    extern __shared__ __align__(16) char smem[];
    const uint32_t sb = smem_u32(smem);
    const int tid = threadIdx.x, wid = tid >> 5, lane = tid & 31;

    const float* __restrict__ src = g_ta;
    float* __restrict__ out = g_tb;

    for (int i = tid; i < (128 * ROWB) / 16; i += 512) {
        ((float4*)(smem + F2_BHI))[i] = ((const float4*)g_Bh2)[i];
        ((float4*)(smem + F2_BLO))[i] = ((const float4*)g_Bl2)[i];
    }

    const int m0 = (wid & 3) * 16;       // 0,16,32,48
    const int n0 = (wid >> 2) * 32;      // 0,32,64,96
    const int a_r = lane & 15, a_kh = lane >> 4;
    const int b_r = lane & 7,  b_kh = (lane >> 3) & 1;

    const float4 bv = __ldg((const float4*)bias + lane);

    for (int tile = blockIdx.x; tile < NTILES64; tile += gridDim.x) {
        const int row0 = tile * 64;

        // ---- gather phase: warp w -> rows w*4 .. w*4+3 (8-edge unrolled) ----
#pragma unroll
        for (int r4 = 0; r4 < 4; r4++) {
            int lr = wid * 4 + r4;
            int node = row0 + lr;
            float4 acc = make_float4(0.f, 0.f, 0.f, 0.f);
            if (node < M) {
                int beg = g_rowptr[node], end = g_rowptr[node + 1];
                int e = beg;
                for (; e + 8 <= end; e += 8) {
                    int s[8];
#pragma unroll
                    for (int j = 0; j < 8; j++) s[j] = __ldg(g_adj + e + j);
                    float4 v[8];
#pragma unroll
                    for (int j = 0; j < 8; j++)
                        v[j] = __ldg((const float4*)(src + (size_t)s[j] * FDIM) + lane);
#pragma unroll
                    for (int j = 0; j < 8; j++) {
                        acc.x += v[j].x; acc.y += v[j].y;
                        acc.z += v[j].z; acc.w += v[j].w;
                    }
                }
                for (; e + 2 <= end; e += 2) {
                    int s0 = __ldg(g_adj + e), s1 = __ldg(g_adj + e + 1);
                    float4 v0 = __ldg((const float4*)(src + (size_t)s0 * FDIM) + lane);
                    float4 v1 = __ldg((const float4*)(src + (size_t)s1 * FDIM) + lane);
                    acc.x += v0.x + v1.x; acc.y += v0.y + v1.y;
                    acc.z += v0.z + v1.z; acc.w += v0.w + v1.w;
                }
                if (e < end) {
                    int s0 = __ldg(g_adj + e);
                    float4 v0 = __ldg((const float4*)(src + (size_t)s0 * FDIM) + lane);
                    acc.x += v0.x; acc.y += v0.y; acc.z += v0.z; acc.w += v0.w;
                }
                float dn = g_dinv[node];
                acc.x = fmaf(acc.x, dn, bv.x);
                acc.y = fmaf(acc.y, dn, bv.y);
                acc.z = fmaf(acc.z, dn, bv.z);
                acc.w = fmaf(acc.w, dn, bv.w);
                acc.x = fmaxf(acc.x, 0.f); acc.y = fmaxf(acc.y, 0.f);
                acc.z = fmaxf(acc.z, 0.f); acc.w = fmaxf(acc.w, 0.f);
            }
            uint2 hi, lo; split4(acc, hi, lo);
            int off = lr * ROWB + lane * 8;
            *(uint2*)(smem + F2_AHI + off) = hi;
            *(uint2*)(smem + F2_ALO + off) = lo;
        }
        __syncthreads();

        // ---- MMA phase: 16x32 per warp ----
        float acc[4][4];
#pragma unroll
        for (int nt = 0; nt < 4; nt++)
#pragma unroll
            for (int j = 0; j < 4; j++) acc[nt][j] = 0.f;

#pragma unroll
        for (int ks = 0; ks < 8; ks++) {
            const int k0 = ks * 16;
            uint32_t ah[4], al[4];
            uint32_t aoff = (uint32_t)((m0 + a_r) * ROWB + (k0 + a_kh * 8) * 2);
            ldsm_x4(ah[0], ah[1], ah[2], ah[3], sb + F2_AHI + aoff);
            ldsm_x4(al[0], al[1], al[2], al[3], sb + F2_ALO + aoff);
#pragma unroll
            for (int nt = 0; nt < 4; nt++) {
                uint32_t boff = (uint32_t)((n0 + nt * 8 + b_r) * ROWB + (k0 + b_kh * 8) * 2);
                uint32_t bh0, bh1, bl0, bl1;
                ldsm_x2(bh0, bh1, sb + F2_BHI + boff);
                ldsm_x2(bl0, bl1, sb + F2_BLO + boff);
                mma_bf16(acc[nt][0], acc[nt][1], acc[nt][2], acc[nt][3],
                         ah[0], ah[1], ah[2], ah[3], bh0, bh1);
                mma_bf16(acc[nt][0], acc[nt][1], acc[nt][2], acc[nt][3],
                         ah[0], ah[1], ah[2], ah[3], bl0, bl1);
                mma_bf16(acc[nt][0], acc[nt][1], acc[nt][2], acc[nt][3],
                         al[0], al[1], al[2], al[3], bh0, bh1);
            }
        }
        __syncthreads();

        // ---- epilogue ----
        const int qr = lane >> 2, qc = (lane & 3) * 2;
        int r_a = row0 + m0 + qr, r_b = r_a + 8;
        float dna = (r_a < M) ? g_dinv[r_a] : 0.f;
        float dnb = (r_b < M) ? g_dinv[r_b] : 0.f;
#pragma unroll
        for (int nt = 0; nt < 4; nt++) {
            int col = n0 + nt * 8 + qc;
            if (r_a < M)
                *(float2*)(out + (size_t)r_a * FDIM + col) =
                    make_float2(acc[nt][0] * dna, acc[nt][1] * dna);
            if (r_b < M)
                *(float2*)(out + (size_t)r_b * FDIM + col) =
                    make_float2(acc[nt][2] * dnb, acc[nt][3] * dnb);
        }
    }
}

// ---------------- GEMM3: u = t2 @ W3 (plain, 40-wide, u stored in g_ta) ----------------
__global__ void __launch_bounds__(512, 2)
gemm3_kernel(int M) {
    extern __shared__ __align__(16) char smem[];
    const int BBYTES = 40 * ROWB;
    const int BLO_OFF = BHI_OFF + BBYTES;
    const uint32_t sb = smem_u32(smem);
    const int tid = threadIdx.x, wid = tid >> 5, lane = tid & 31;

    const float* __restrict__ A = g_tb;
    float* __restrict__ out = g_ta;   // u, row stride NCLS

    for (int i = tid; i < BBYTES / 16; i += 512) {
        ((float4*)(smem + BHI_OFF))[i] = ((const float4*)g_Bh3)[i];
        ((float4*)(smem + BLO_OFF))[i] = ((const float4*)g_Bl3)[i];
    }

    const int m0 = (wid & 7) * 16;
    const int nhalf = wid >> 3;
    const int n0 = nhalf * 24;
    const int NT = nhalf ? 2 : 3;
    const int a_r = lane & 15, a_kh = lane >> 4;
    const int b_r = lane & 7,  b_kh = (lane >> 3) & 1;

    for (int tile = blockIdx.x; tile < NTILES; tile += gridDim.x) {
        const int row0 = tile * 128;

#pragma unroll
        for (int i = 0; i < 8; i++) {
            int idx = tid + i * 512;
            int r = idx >> 5, c4 = (idx & 31) << 2;
            int grow = row0 + r;
            float4 v = make_float4(0.f, 0.f, 0.f, 0.f);
            if (grow < M) v = *(const float4*)(A + (size_t)grow * FDIM + c4);
            uint2 hi, lo; split4(v, hi, lo);
            int off = r * ROWB + c4 * 2;
            *(uint2*)(smem + AHI_OFF + off) = hi;
            *(uint2*)(smem + ALO_OFF + off) = lo;
        }
        __syncthreads();

        float acc[3][4];
#pragma unroll
        for (int nt = 0; nt < 3; nt++)
#pragma unroll
            for (int j = 0; j < 4; j++) acc[nt][j] = 0.f;

#pragma unroll
        for (int ks = 0; ks < 8; ks++) {
            const int k0 = ks * 16;
            uint32_t ah[4], al[4];
            uint32_t aoff = (uint32_t)((m0 + a_r) * ROWB + (k0 + a_kh * 8) * 2);
            ldsm_x4(ah[0], ah[1], ah[2], ah[3], sb + AHI_OFF + aoff);
            ldsm_x4(al[0], al[1], al[2], al[3], sb + ALO_OFF + aoff);
#pragma unroll
            for (int nt = 0; nt < 3; nt++) {
                if (nt >= NT) break;
                uint32_t boff = (uint32_t)((n0 + nt * 8 + b_r) * ROWB + (k0 + b_kh * 8) * 2);
                uint32_t bh0, bh1, bl0, bl1;
                ldsm_x2(bh0, bh1, sb + BHI_OFF + boff);
                ldsm_x2(bl0, bl1, sb + BLO_OFF + boff);
                mma_bf16(acc[nt][0], acc[nt][1], acc[nt][2], acc[nt][3],
                         ah[0], ah[1], ah[2], ah[3], bh0, bh1);
                mma_bf16(acc[nt][0], acc[nt][1], acc[nt][2], acc[nt][3],
                         ah[0], ah[1], ah[2], ah[3], bl0, bl1);
                mma_bf16(acc[nt][0], acc[nt][1], acc[nt][2], acc[nt][3],
                         al[0], al[1], al[2], al[3], bh0, bh1);
            }
        }
        __syncthreads();

        const int qr = lane >> 2, qc = (lane & 3) * 2;
        int r_a = row0 + m0 + qr, r_b = r_a + 8;
#pragma unroll
        for (int nt = 0; nt < 3; nt++) {
            if (nt >= NT) break;
            int col = n0 + nt * 8 + qc;
            if (r_a < M)
                *(float2*)(out + (size_t)r_a * NCLS + col) =
                    make_float2(acc[nt][0], acc[nt][1]);
            if (r_b < M)
                *(float2*)(out + (size_t)r_b * NCLS + col) =
                    make_float2(acc[nt][2], acc[nt][3]);
        }
    }
}

// ---------------- agg40a: l = dinv*(dinv*agg(u) + c), float2 lanes 0..19 ----------------
__global__ void __launch_bounds__(256)
agg40a_kernel() {
    int node = blockIdx.x * (blockDim.x >> 5) + (threadIdx.x >> 5);
    if (node >= NN) return;
    int lane = threadIdx.x & 31;
    const float* __restrict__ u = g_ta;
    const bool act = (lane < 20);

    int beg = g_rowptr[node], end = g_rowptr[node + 1];
    float a0 = 0.f, a1 = 0.f;
    int e = beg;
    for (; e + 8 <= end; e += 8) {
        int s[8];
#pragma unroll
        for (int j = 0; j < 8; j++) s[j] = __ldg(g_adj + e + j);
        float2 v[8];
#pragma unroll
        for (int j = 0; j < 8; j++)
            v[j] = act ? __ldg((const float2*)(u + (size_t)s[j] * NCLS) + lane)
                       : make_float2(0.f, 0.f);
#pragma unroll
        for (int j = 0; j < 8; j++) { a0 += v[j].x; a1 += v[j].y; }
    }
    for (; e < end; e++) {
        int s = __ldg(g_adj + e);
        if (act) {
            float2 v = __ldg((const float2*)(u + (size_t)s * NCLS) + lane);
            a0 += v.x; a1 += v.y;
        }
    }

    if (act) {
        float dn = g_dinv[node];
        float2 c = __ldg((const float2*)g_c + lane);
        float2 o;
        o.x = dn * (dn * a0 + c.x);
        o.y = dn * (dn * a1 + c.y);
        *((float2*)(g_l + (size_t)node * NCLS) + lane) = o;
    }
}

// ---------------- aggregation 40-wide + fused log_softmax (float2 lanes) ----------------
__global__ void __launch_bounds__(256)
agg40_lsm_kernel(const float* __restrict__ b3, float* __restrict__ out) {
    int node = blockIdx.x * (blockDim.x >> 5) + (threadIdx.x >> 5);
    if (node >= NN) return;
    int lane = threadIdx.x & 31;
    const bool act = (lane < 20);

    int beg = g_rowptr[node], end = g_rowptr[node + 1];
    float a0 = 0.f, a1 = 0.f;
    int e = beg;
    for (; e + 8 <= end; e += 8) {
        int s[8];
#pragma unroll
        for (int j = 0; j < 8; j++) s[j] = __ldg(g_adj + e + j);
        float2 v[8];
#pragma unroll
        for (int j = 0; j < 8; j++)
            v[j] = act ? __ldg((const float2*)(g_l + (size_t)s[j] * NCLS) + lane)
                       : make_float2(0.f, 0.f);
#pragma unroll
        for (int j = 0; j < 8; j++) { a0 += v[j].x; a1 += v[j].y; }
    }
    for (; e < end; e++) {
        int s = __ldg(g_adj + e);
        if (act) {
            float2 v = __ldg((const float2*)(g_l + (size_t)s * NCLS) + lane);
            a0 += v.x; a1 += v.y;
        }
    }

    float dn = g_dinv[node];
    float v0 = -1e30f, v1 = -1e30f;
    if (act) {
        float2 b = __ldg((const float2*)b3 + lane);
        v0 = a0 * dn + b.x;
        v1 = a1 * dn + b.y;
    }

    float m = fmaxf(v0, v1);
#pragma unroll
    for (int off = 16; off; off >>= 1)
        m = fmaxf(m, __shfl_xor_sync(0xffffffffu, m, off));
    float s = act ? (__expf(v0 - m) + __expf(v1 - m)) : 0.f;
#pragma unroll
    for (int off = 16; off; off >>= 1)
        s += __shfl_xor_sync(0xffffffffu, s, off);
    float L = __logf(s) + m;

    if (act)
        *((float2*)(out + (size_t)node * NCLS) + lane) =
            make_float2(v0 - L, v1 - L);
}

// ---------------- launch ----------------
extern "C" void kernel_launch(void* const* d_in, const int* in_sizes, int n_in,
                              void* d_out, int out_size) {
    const float* x  = (const float*)d_in[0];
    const int*   ei = (const int*)d_in[1];
    const float* W1 = (const float*)d_in[2];
    const float* b1 = (const float*)d_in[3];
    const float* W2 = (const float*)d_in[4];
    const float* b2 = (const float*)d_in[5];
    const float* W3 = (const float*)d_in[6];
    const float* b3 = (const float*)d_in[7];
    float* out = (float*)d_out;

    const int gN   = (NN + 255) / 256;
    const int gE   = (NE + 255) / 256;
    const int gET  = (ET + 255) / 256;
    const int gAgg = (NN + 7) / 8;

    const int SMEM128 = BHI_OFF + 2 * 128 * ROWB;  // 139264
    const int SMEM40  = BHI_OFF + 2 * 40 * ROWB;   //  91392
    cudaFuncSetAttribute(gemm1_kernel,
                         cudaFuncAttributeMaxDynamicSharedMemorySize, SMEM128);
    cudaFuncSetAttribute(fused2_kernel,
                         cudaFuncAttributeMaxDynamicSharedMemorySize, F2_SMEM);
    cudaFuncSetAttribute(gemm3_kernel,
                         cudaFuncAttributeMaxDynamicSharedMemorySize, SMEM40);

    // --- graph preprocessing ---
    init_deg_kernel<<<gN, 256>>>(ei);
    count_deg_kernel<<<gE, 256>>>(ei);
    scan1_kernel<<<NB_SCAN, SCAN_BLK>>>();
    scan3_kernel<<<NB_SCAN, 256>>>();
    fill_adj_kernel<<<gET, 256>>>(ei);

    // --- weight pre-pack + c = b2@W3 (single launch) ---
    pack_all_kernel<<<149, 256>>>(W1, W2, W3, b2);

    // --- layer 1: t1 = dinv*(x@W1) ---
    gemm1_kernel<<<148, 512, SMEM128>>>(x, NN);

    // --- layer 2 fused (64-row tiles, 2 CTAs/SM) ---
    fused2_kernel<<<296, 512, F2_SMEM>>>(b1, NN);

    // --- layer 3 restructured (linearity): u = t2@W3, then 40-wide agg ---
    gemm3_kernel<<<296, 512, SMEM40>>>(NN);
    agg40a_kernel<<<gAgg, 256>>>();

    // --- final aggregation + log_softmax ---
    agg40_lsm_kernel<<<gAgg, 256>>>(b3, out);

    (void)in_sizes; (void)n_in; (void)out_size;
}